// round 9
// baseline (speedup 1.0000x reference)
#include <cuda_runtime.h>
#include <cuda_bf16.h>
#include <cstdint>
#include <math.h>

#define N 8192
#define D 64
#define SCALE 0.125f      // 1/sqrt(64)
#define LSTRIDE 72        // smem row stride in bf16 (144B, conflict-free)
#define LS32 36           // row stride in u32 words
#define RB 144            // row stride in bytes

// ---------------------------------------------------------------------------
// global scratch (no allocation allowed) -- all row-major [n][64] bf16 splits
// ---------------------------------------------------------------------------
__device__ __nv_bfloat16 g_qhi[2][N * D];
__device__ __nv_bfloat16 g_qlo[2][N * D];
__device__ __nv_bfloat16 g_khi[2][N * D];
__device__ __nv_bfloat16 g_klo[2][N * D];
__device__ __nv_bfloat16 g_vhi[2][N * D];    // V (inputs) split, row-major
__device__ __nv_bfloat16 g_vlo[2][N * D];
__device__ __nv_bfloat16 g_atthi[2][N * D];
__device__ __nv_bfloat16 g_attlo[2][N * D];
__device__ float g_norm2[2][N];

// ---------------------------------------------------------------------------
// helpers
// ---------------------------------------------------------------------------
__device__ __forceinline__ uint32_t smem_u32(const void* p) {
    uint32_t a;
    asm("{ .reg .u64 t; cvta.to.shared.u64 t, %1; cvt.u32.u64 %0, t; }" : "=r"(a) : "l"(p));
    return a;
}
__device__ __forceinline__ void mma16816(float* c, const uint32_t* a, const uint32_t* b) {
    asm volatile(
        "mma.sync.aligned.m16n8k16.row.col.f32.bf16.bf16.f32 "
        "{%0,%1,%2,%3}, {%4,%5,%6,%7}, {%8,%9}, {%0,%1,%2,%3};\n"
        : "+f"(c[0]), "+f"(c[1]), "+f"(c[2]), "+f"(c[3])
        : "r"(a[0]), "r"(a[1]), "r"(a[2]), "r"(a[3]), "r"(b[0]), "r"(b[1]));
}
__device__ __forceinline__ void ldmx4(uint32_t* r, uint32_t saddr) {
    asm volatile("ldmatrix.sync.aligned.m8n8.x4.shared.b16 {%0,%1,%2,%3}, [%4];"
        : "=r"(r[0]), "=r"(r[1]), "=r"(r[2]), "=r"(r[3]) : "r"(saddr));
}
__device__ __forceinline__ void ldmx4t(uint32_t* r, uint32_t saddr) {
    asm volatile("ldmatrix.sync.aligned.m8n8.x4.trans.shared.b16 {%0,%1,%2,%3}, [%4];"
        : "=r"(r[0]), "=r"(r[1]), "=r"(r[2]), "=r"(r[3]) : "r"(saddr));
}
__device__ __forceinline__ void cp16(uint32_t saddr, const void* gaddr) {
    asm volatile("cp.async.cg.shared.global [%0], [%1], 16;" :: "r"(saddr), "l"(gaddr));
}
#define CP_COMMIT() asm volatile("cp.async.commit_group;" ::: "memory")
template <int n>
__device__ __forceinline__ void cp_wait() {
    asm volatile("cp.async.wait_group %0;" :: "n"(n) : "memory");
}
__device__ __forceinline__ uint32_t pack_bf16x2(float lo, float hi) {
    uint32_t r;
    asm("cvt.rn.bf16x2.f32 %0, %1, %2;" : "=r"(r) : "f"(hi), "f"(lo));
    return r;
}
__device__ __forceinline__ float lo_bf16(uint32_t p) { return __uint_as_float(p << 16); }
__device__ __forceinline__ float hi_bf16(uint32_t p) { return __uint_as_float(p & 0xFFFF0000u); }

// ---------------------------------------------------------------------------
// kernel 1: Q/K projection + bf16 splits. 512 blocks x 32 rows.
// Each thread: 1 column x 8 rows (16 accumulators) -> low regs, high occupancy.
// ---------------------------------------------------------------------------
__global__ __launch_bounds__(256) void prep_kernel(const float* __restrict__ x,
                                                   const float* __restrict__ y,
                                                   const float* __restrict__ Wq,
                                                   const float* __restrict__ Wk) {
    __shared__ float sW[2][D * D];   // 32KB
    __shared__ float sIn[32][D];     // 8KB
    int tid = threadIdx.x;
    int b = blockIdx.x;
    int which = (b >= 256) ? 1 : 0;
    const float* in = which ? y : x;
    int row0 = (b & 255) * 32;

    for (int i = tid; i < D * D; i += 256) { sW[0][i] = Wq[i]; sW[1][i] = Wk[i]; }
    for (int u = tid; u < 32 * D; u += 256)
        ((float*)sIn)[u] = in[(size_t)row0 * D + u];
    __syncthreads();

    int c = tid & 63;
    int rg = tid >> 6;          // 0..3, 8 rows each
    float accq[8] = {}, acck[8] = {};
#pragma unroll
    for (int k = 0; k < D; k++) {
        float wq = sW[0][k * D + c];
        float wk = sW[1][k * D + c];
#pragma unroll
        for (int i = 0; i < 8; i++) {
            float v = sIn[rg * 8 + i][k];
            accq[i] = fmaf(v, wq, accq[i]);
            acck[i] = fmaf(v, wk, acck[i]);
        }
    }
#pragma unroll
    for (int i = 0; i < 8; i++) {
        int n = row0 + rg * 8 + i;
        __nv_bfloat16 h;
        h = __float2bfloat16(accq[i]);
        g_qhi[which][(size_t)n * D + c] = h;
        g_qlo[which][(size_t)n * D + c] = __float2bfloat16(accq[i] - __bfloat162float(h));
        h = __float2bfloat16(acck[i]);
        g_khi[which][(size_t)n * D + c] = h;
        g_klo[which][(size_t)n * D + c] = __float2bfloat16(acck[i] - __bfloat162float(h));
    }
    // V splits, coalesced bf16x2 writes
    uint32_t* vh = (uint32_t*)g_vhi[which];
    uint32_t* vl = (uint32_t*)g_vlo[which];
    for (int u = tid; u < 1024; u += 256) {
        int r = u >> 5, cc = (u & 31) * 2;
        float v0 = sIn[r][cc], v1 = sIn[r][cc + 1];
        uint32_t h = pack_bf16x2(v0, v1);
        size_t idx = ((size_t)(row0 + r) * D + cc) >> 1;
        vh[idx] = h;
        vl[idx] = pack_bf16x2(v0 - lo_bf16(h), v1 - hi_bf16(h));
    }
}

// ---------------------------------------------------------------------------
// kernel 2: single-pass flash attention, depth-3 cp.async ring, 1 barrier/iter
// CTA: 256 threads (8 warps), 128 query rows, 64-key tiles, 128 iterations.
// Grid = 128 CTAs -> 1 per SM, halved L2 K/V traffic vs 64-row CTAs.
// ---------------------------------------------------------------------------
#define TILE_B 36864   // per-buffer: 4 arrays x 64 rows x 144B
#define OFF_KH 0
#define OFF_KL 9216
#define OFF_VH 18432
#define OFF_VL 27648
#define SMEM_FLASH (3 * TILE_B)

__device__ __forceinline__ void flash_issue_tile(uint32_t sbu, int buf,
                                                 int which, int j0, int tid) {
    uint32_t bo = sbu + (uint32_t)buf * TILE_B;
#pragma unroll
    for (int u = tid; u < 512; u += 256) {
        int r = u >> 3, ch = u & 7;
        uint32_t so = (uint32_t)r * RB + (uint32_t)ch * 16;
        cp16(bo + OFF_KH + so, g_khi[which] + (size_t)(j0 + r) * D + ch * 8);
        cp16(bo + OFF_KL + so, g_klo[which] + (size_t)(j0 + r) * D + ch * 8);
        cp16(bo + OFF_VH + so, g_vhi[which] + (size_t)(j0 + r) * D + ch * 8);
        cp16(bo + OFF_VL + so, g_vlo[which] + (size_t)(j0 + r) * D + ch * 8);
    }
    CP_COMMIT();
}

__global__ __launch_bounds__(256, 1) void flash_mma_kernel() {
    extern __shared__ char smf[];
    uint32_t sbu = smem_u32(smf);

    int tid = threadIdx.x;
    int w = tid >> 5, lane = tid & 31;
    int q = lane >> 2, c = lane & 3;
    int which = blockIdx.x >> 6;
    int q0 = (blockIdx.x & 63) * 128;
    int rowA = w * 16 + q;

    // stage Q tile (128 rows hi at +0, lo at +18432) into buf0, extract A frags
    for (int u = tid; u < 1024; u += 256) {
        int r = u >> 3, ch = u & 7;
        *(uint4*)(smf + r * RB + ch * 16) =
            ((const uint4*)(g_qhi[which] + (size_t)(q0 + r) * D))[ch];
        *(uint4*)(smf + 18432 + r * RB + ch * 16) =
            ((const uint4*)(g_qlo[which] + (size_t)(q0 + r) * D))[ch];
    }
    __syncthreads();

    uint32_t aq[2][4][4];
    {
        const uint32_t* ph = (const uint32_t*)smf;
        const uint32_t* pl = (const uint32_t*)(smf + 18432);
#pragma unroll
        for (int kk = 0; kk < 4; kk++) {
            int col = kk * 8 + c;
            aq[0][kk][0] = ph[rowA * LS32 + col];
            aq[0][kk][1] = ph[(rowA + 8) * LS32 + col];
            aq[0][kk][2] = ph[rowA * LS32 + col + 4];
            aq[0][kk][3] = ph[(rowA + 8) * LS32 + col + 4];
            aq[1][kk][0] = pl[rowA * LS32 + col];
            aq[1][kk][1] = pl[(rowA + 8) * LS32 + col];
            aq[1][kk][2] = pl[rowA * LS32 + col + 4];
            aq[1][kk][3] = pl[(rowA + 8) * LS32 + col + 4];
        }
    }
    __syncthreads();

    // prologue: prefetch tiles 0 and 1
    flash_issue_tile(sbu, 0, which, 0, tid);
    flash_issue_tile(sbu, 1, which, 64, tid);

    float o[8][4] = {};
    float m0 = -INFINITY, m1 = -INFINITY, l0 = 0.f, l1 = 0.f;
    uint32_t lmoff = (uint32_t)(lane & 7) * RB + (uint32_t)(lane >> 3) * 16;

    int bi = 0, bi2 = 2;   // current buffer, prefetch buffer
    for (int t = 0; t < 128; t++) {
        if (t < 126) cp_wait<1>(); else cp_wait<0>();
        __syncthreads();
        if (t + 2 < 128) flash_issue_tile(sbu, bi2, which, (t + 2) * 64, tid);
        uint32_t bufb = sbu + (uint32_t)bi * TILE_B;
        bi = (bi == 2) ? 0 : bi + 1;
        bi2 = (bi2 == 2) ? 0 : bi2 + 1;

        // ---- S = Q K^T (3 split passes: hh, hl, lh) ----
        float sc[8][4] = {};
#pragma unroll
        for (int nt = 0; nt < 8; nt++) {
            uint32_t a0 = bufb + (uint32_t)nt * (8 * RB) + lmoff;
            uint32_t bh[4][2], bl[4][2];
            ldmx4(&bh[0][0], a0 + OFF_KH);
            ldmx4(&bh[2][0], a0 + OFF_KH + 64);
            ldmx4(&bl[0][0], a0 + OFF_KL);
            ldmx4(&bl[2][0], a0 + OFF_KL + 64);
#pragma unroll
            for (int kk = 0; kk < 4; kk++) mma16816(sc[nt], aq[0][kk], bh[kk]);
#pragma unroll
            for (int kk = 0; kk < 4; kk++) mma16816(sc[nt], aq[0][kk], bl[kk]);
#pragma unroll
            for (int kk = 0; kk < 4; kk++) mma16816(sc[nt], aq[1][kk], bh[kk]);
        }

        // ---- online softmax ----
        float mx0 = -INFINITY, mx1 = -INFINITY;
#pragma unroll
        for (int nt = 0; nt < 8; nt++) {
            mx0 = fmaxf(mx0, fmaxf(sc[nt][0], sc[nt][1]));
            mx1 = fmaxf(mx1, fmaxf(sc[nt][2], sc[nt][3]));
        }
        mx0 = fmaxf(mx0, __shfl_xor_sync(0xffffffffu, mx0, 1));
        mx0 = fmaxf(mx0, __shfl_xor_sync(0xffffffffu, mx0, 2));
        mx1 = fmaxf(mx1, __shfl_xor_sync(0xffffffffu, mx1, 1));
        mx1 = fmaxf(mx1, __shfl_xor_sync(0xffffffffu, mx1, 2));
        float m0n = fmaxf(m0, mx0), m1n = fmaxf(m1, mx1);
        float f0 = __expf(SCALE * (m0 - m0n));
        float f1 = __expf(SCALE * (m1 - m1n));
        m0 = m0n; m1 = m1n;
        l0 *= f0; l1 *= f1;

        uint32_t pah[8], pbh[8], pal[8], pbl[8];
#pragma unroll
        for (int nt = 0; nt < 8; nt++) {
            float p0 = __expf(SCALE * (sc[nt][0] - m0));
            float p1 = __expf(SCALE * (sc[nt][1] - m0));
            float p2 = __expf(SCALE * (sc[nt][2] - m1));
            float p3 = __expf(SCALE * (sc[nt][3] - m1));
            l0 += p0 + p1; l1 += p2 + p3;
            uint32_t h = pack_bf16x2(p0, p1);
            pah[nt] = h;
            pal[nt] = pack_bf16x2(p0 - lo_bf16(h), p1 - hi_bf16(h));
            h = pack_bf16x2(p2, p3);
            pbh[nt] = h;
            pbl[nt] = pack_bf16x2(p2 - lo_bf16(h), p3 - hi_bf16(h));
            o[nt][0] *= f0; o[nt][1] *= f0; o[nt][2] *= f1; o[nt][3] *= f1;
        }

        // ---- O += P V (3 split passes), row-major V via ldmatrix.trans ----
#pragma unroll
        for (int nt = 0; nt < 8; nt++) {
            uint32_t av = bufb + OFF_VH + (uint32_t)lane * RB + (uint32_t)nt * 16;
            uint32_t vbh[4][2], vbl[4][2];
            ldmx4t(&vbh[0][0], av);
            ldmx4t(&vbh[2][0], av + 32 * RB);
            ldmx4t(&vbl[0][0], av + (OFF_VL - OFF_VH));
            ldmx4t(&vbl[2][0], av + (OFF_VL - OFF_VH) + 32 * RB);
#pragma unroll
            for (int kk = 0; kk < 4; kk++) {
                uint32_t Ah[4] = {pah[2 * kk], pbh[2 * kk], pah[2 * kk + 1], pbh[2 * kk + 1]};
                uint32_t Al[4] = {pal[2 * kk], pbl[2 * kk], pal[2 * kk + 1], pbl[2 * kk + 1]};
                mma16816(o[nt], Ah, vbh[kk]);
                mma16816(o[nt], Ah, vbl[kk]);
                mma16816(o[nt], Al, vbh[kk]);
            }
        }
    }

    // ---- epilogue ----
    l0 += __shfl_xor_sync(0xffffffffu, l0, 1);
    l0 += __shfl_xor_sync(0xffffffffu, l0, 2);
    l1 += __shfl_xor_sync(0xffffffffu, l1, 1);
    l1 += __shfl_xor_sync(0xffffffffu, l1, 2);
    float inv0 = 1.0f / l0, inv1 = 1.0f / l1;
    float n0 = 0.f, n1 = 0.f;
    int row = q0 + rowA;
    uint32_t* dh = (uint32_t*)g_atthi[which];
    uint32_t* dl = (uint32_t*)g_attlo[which];
#pragma unroll
    for (int nt = 0; nt < 8; nt++) {
        float o0 = o[nt][0] * inv0, o1 = o[nt][1] * inv0;
        float o2 = o[nt][2] * inv1, o3 = o[nt][3] * inv1;
        n0 = fmaf(o0, o0, fmaf(o1, o1, n0));
        n1 = fmaf(o2, o2, fmaf(o3, o3, n1));
        uint32_t h = pack_bf16x2(o0, o1);
        dh[(size_t)row * 32 + nt * 4 + c] = h;
        dl[(size_t)row * 32 + nt * 4 + c] = pack_bf16x2(o0 - lo_bf16(h), o1 - hi_bf16(h));
        h = pack_bf16x2(o2, o3);
        dh[(size_t)(row + 8) * 32 + nt * 4 + c] = h;
        dl[(size_t)(row + 8) * 32 + nt * 4 + c] = pack_bf16x2(o2 - lo_bf16(h), o3 - hi_bf16(h));
    }
    n0 += __shfl_xor_sync(0xffffffffu, n0, 1);
    n0 += __shfl_xor_sync(0xffffffffu, n0, 2);
    n1 += __shfl_xor_sync(0xffffffffu, n1, 1);
    n1 += __shfl_xor_sync(0xffffffffu, n1, 2);
    if (c == 0) {
        g_norm2[which][row] = n0;
        g_norm2[which][row + 8] = n1;
    }
}

// ---------------------------------------------------------------------------
// kernel 3: pairwise RBF via mma.sync, 128x128 tile per CTA (256 threads)
// 3-pass split; 4x fewer CTAs and 4x less L2 load traffic than 64x64.
// ---------------------------------------------------------------------------
#define PW_AH 0
#define PW_AL 18432
#define PW_BH 36864
#define PW_BL 55296
#define PW_YN 73728
#define SMEM_PW (73728 + 512)

__global__ __launch_bounds__(256) void pairwise_mma_kernel(float* __restrict__ out) {
    extern __shared__ char smp[];
    uint32_t sbu = smem_u32(smp);

    int tid = threadIdx.x;
    int w = tid >> 5, lane = tid & 31;
    int q = lane >> 2, c = lane & 3;
    int m0 = blockIdx.y * 128;
    int j0 = blockIdx.x * 128;
    int rowA = w * 16 + q;

    for (int u = tid; u < 1024; u += 256) {
        int r = u >> 3, ch = u & 7;
        uint32_t so = (uint32_t)r * RB + (uint32_t)ch * 16;
        *(uint4*)(smp + PW_AH + so) = ((const uint4*)(g_atthi[0] + (size_t)(m0 + r) * D))[ch];
        *(uint4*)(smp + PW_AL + so) = ((const uint4*)(g_attlo[0] + (size_t)(m0 + r) * D))[ch];
        *(uint4*)(smp + PW_BH + so) = ((const uint4*)(g_atthi[1] + (size_t)(j0 + r) * D))[ch];
        *(uint4*)(smp + PW_BL + so) = ((const uint4*)(g_attlo[1] + (size_t)(j0 + r) * D))[ch];
    }
    float* syn = (float*)(smp + PW_YN);
    if (tid < 128) syn[tid] = g_norm2[1][j0 + tid];
    __syncthreads();

    uint32_t aq[2][4][4];
    {
        const uint32_t* ph = (const uint32_t*)(smp + PW_AH);
        const uint32_t* pl = (const uint32_t*)(smp + PW_AL);
#pragma unroll
        for (int kk = 0; kk < 4; kk++) {
            int col = kk * 8 + c;
            aq[0][kk][0] = ph[rowA * LS32 + col];
            aq[0][kk][1] = ph[(rowA + 8) * LS32 + col];
            aq[0][kk][2] = ph[rowA * LS32 + col + 4];
            aq[0][kk][3] = ph[(rowA + 8) * LS32 + col + 4];
            aq[1][kk][0] = pl[rowA * LS32 + col];
            aq[1][kk][1] = pl[(rowA + 8) * LS32 + col];
            aq[1][kk][2] = pl[rowA * LS32 + col + 4];
            aq[1][kk][3] = pl[(rowA + 8) * LS32 + col + 4];
        }
    }

    uint32_t sbh = sbu + PW_BH, sbl = sbu + PW_BL;
    uint32_t lmoff = (uint32_t)(lane & 7) * RB + (uint32_t)(lane >> 3) * 16;
    float acc[16][4] = {};
#pragma unroll
    for (int nt = 0; nt < 16; nt++) {
        uint32_t ro = (uint32_t)nt * (8 * RB) + lmoff;
        uint32_t bh[4][2], bl[4][2];
        ldmx4(&bh[0][0], sbh + ro);
        ldmx4(&bh[2][0], sbh + ro + 64);
        ldmx4(&bl[0][0], sbl + ro);
        ldmx4(&bl[2][0], sbl + ro + 64);
#pragma unroll
        for (int kk = 0; kk < 4; kk++) mma16816(acc[nt], aq[0][kk], bh[kk]);
#pragma unroll
        for (int kk = 0; kk < 4; kk++) mma16816(acc[nt], aq[0][kk], bl[kk]);
#pragma unroll
        for (int kk = 0; kk < 4; kk++) mma16816(acc[nt], aq[1][kk], bh[kk]);
    }

    int rowx = m0 + rowA;
    float xn0 = g_norm2[0][rowx];
    float xn1 = g_norm2[0][rowx + 8];
#pragma unroll
    for (int nt = 0; nt < 16; nt++) {
        int cb = nt * 8 + 2 * c;
        float y0 = syn[cb], y1 = syn[cb + 1];
        float2 e;
        e.x = __expf(-(xn0 + y0 - 2.f * acc[nt][0]));
        e.y = __expf(-(xn0 + y1 - 2.f * acc[nt][1]));
        *reinterpret_cast<float2*>(out + (size_t)rowx * N + j0 + cb) = e;
        e.x = __expf(-(xn1 + y0 - 2.f * acc[nt][2]));
        e.y = __expf(-(xn1 + y1 - 2.f * acc[nt][3]));
        *reinterpret_cast<float2*>(out + (size_t)(rowx + 8) * N + j0 + cb) = e;
    }
}

// ---------------------------------------------------------------------------
extern "C" void kernel_launch(void* const* d_in, const int* in_sizes, int n_in,
                              void* d_out, int out_size) {
    const float* Wq = (const float*)d_in[0];
    const float* Wk = (const float*)d_in[1];
    const float* x  = (const float*)d_in[2];
    const float* y  = (const float*)d_in[3];
    float* out = (float*)d_out;

    prep_kernel<<<512, 256>>>(x, y, Wq, Wk);

    cudaFuncSetAttribute(flash_mma_kernel, cudaFuncAttributeMaxDynamicSharedMemorySize,
                         SMEM_FLASH);
    flash_mma_kernel<<<128, 256, SMEM_FLASH>>>();

    cudaFuncSetAttribute(pairwise_mma_kernel, cudaFuncAttributeMaxDynamicSharedMemorySize,
                         SMEM_PW);
    dim3 grid(N / 128, N / 128);
    pairwise_mma_kernel<<<grid, 256, SMEM_PW>>>(out);
}

// round 10
// speedup vs baseline: 1.0651x; 1.0651x over previous
#include <cuda_runtime.h>
#include <cuda_bf16.h>
#include <cstdint>
#include <math.h>

#define N 8192
#define D 64
#define SCALE 0.125f      // 1/sqrt(64)
#define LSTRIDE 72        // smem row stride in bf16 (144B, conflict-free)
#define LS32 36           // row stride in u32 words
#define RB 144            // row stride in bytes

// ---------------------------------------------------------------------------
// global scratch (no allocation allowed) -- all row-major [n][64] bf16 splits
// ---------------------------------------------------------------------------
__device__ __nv_bfloat16 g_qhi[2][N * D];
__device__ __nv_bfloat16 g_qlo[2][N * D];
__device__ __nv_bfloat16 g_khi[2][N * D];
__device__ __nv_bfloat16 g_klo[2][N * D];
__device__ __nv_bfloat16 g_vhi[2][N * D];    // V (inputs) split, row-major
__device__ __nv_bfloat16 g_vlo[2][N * D];
__device__ __nv_bfloat16 g_atthi[2][N * D];
__device__ __nv_bfloat16 g_attlo[2][N * D];
__device__ float g_norm2[2][N];

// ---------------------------------------------------------------------------
// helpers
// ---------------------------------------------------------------------------
__device__ __forceinline__ uint32_t smem_u32(const void* p) {
    uint32_t a;
    asm("{ .reg .u64 t; cvta.to.shared.u64 t, %1; cvt.u32.u64 %0, t; }" : "=r"(a) : "l"(p));
    return a;
}
__device__ __forceinline__ void mma16816(float* c, const uint32_t* a, const uint32_t* b) {
    asm volatile(
        "mma.sync.aligned.m16n8k16.row.col.f32.bf16.bf16.f32 "
        "{%0,%1,%2,%3}, {%4,%5,%6,%7}, {%8,%9}, {%0,%1,%2,%3};\n"
        : "+f"(c[0]), "+f"(c[1]), "+f"(c[2]), "+f"(c[3])
        : "r"(a[0]), "r"(a[1]), "r"(a[2]), "r"(a[3]), "r"(b[0]), "r"(b[1]));
}
__device__ __forceinline__ void ldmx4(uint32_t* r, uint32_t saddr) {
    asm volatile("ldmatrix.sync.aligned.m8n8.x4.shared.b16 {%0,%1,%2,%3}, [%4];"
        : "=r"(r[0]), "=r"(r[1]), "=r"(r[2]), "=r"(r[3]) : "r"(saddr));
}
__device__ __forceinline__ void ldmx4t(uint32_t* r, uint32_t saddr) {
    asm volatile("ldmatrix.sync.aligned.m8n8.x4.trans.shared.b16 {%0,%1,%2,%3}, [%4];"
        : "=r"(r[0]), "=r"(r[1]), "=r"(r[2]), "=r"(r[3]) : "r"(saddr));
}
__device__ __forceinline__ void cp16(uint32_t saddr, const void* gaddr) {
    asm volatile("cp.async.cg.shared.global [%0], [%1], 16;" :: "r"(saddr), "l"(gaddr));
}
#define CP_COMMIT() asm volatile("cp.async.commit_group;" ::: "memory")
template <int n>
__device__ __forceinline__ void cp_wait() {
    asm volatile("cp.async.wait_group %0;" :: "n"(n) : "memory");
}
__device__ __forceinline__ uint32_t pack_bf16x2(float lo, float hi) {
    uint32_t r;
    asm("cvt.rn.bf16x2.f32 %0, %1, %2;" : "=r"(r) : "f"(hi), "f"(lo));
    return r;
}
__device__ __forceinline__ float lo_bf16(uint32_t p) { return __uint_as_float(p << 16); }
__device__ __forceinline__ float hi_bf16(uint32_t p) { return __uint_as_float(p & 0xFFFF0000u); }

// ---------------------------------------------------------------------------
// kernel 1: Q/K projection + bf16 splits. 512 blocks x 32 rows.
// Each thread: 1 column x 8 rows -> low regs (64), decent occupancy.
// ---------------------------------------------------------------------------
__global__ __launch_bounds__(256) void prep_kernel(const float* __restrict__ x,
                                                   const float* __restrict__ y,
                                                   const float* __restrict__ Wq,
                                                   const float* __restrict__ Wk) {
    __shared__ float sW[2][D * D];   // 32KB
    __shared__ float sIn[32][D];     // 8KB
    int tid = threadIdx.x;
    int b = blockIdx.x;
    int which = (b >= 256) ? 1 : 0;
    const float* in = which ? y : x;
    int row0 = (b & 255) * 32;

    for (int i = tid; i < D * D; i += 256) { sW[0][i] = Wq[i]; sW[1][i] = Wk[i]; }
    for (int u = tid; u < 32 * D; u += 256)
        ((float*)sIn)[u] = in[(size_t)row0 * D + u];
    __syncthreads();

    int c = tid & 63;
    int rg = tid >> 6;          // 0..3, 8 rows each
    float accq[8] = {}, acck[8] = {};
#pragma unroll
    for (int k = 0; k < D; k++) {
        float wq = sW[0][k * D + c];
        float wk = sW[1][k * D + c];
#pragma unroll
        for (int i = 0; i < 8; i++) {
            float v = sIn[rg * 8 + i][k];
            accq[i] = fmaf(v, wq, accq[i]);
            acck[i] = fmaf(v, wk, acck[i]);
        }
    }
#pragma unroll
    for (int i = 0; i < 8; i++) {
        int n = row0 + rg * 8 + i;
        __nv_bfloat16 h;
        h = __float2bfloat16(accq[i]);
        g_qhi[which][(size_t)n * D + c] = h;
        g_qlo[which][(size_t)n * D + c] = __float2bfloat16(accq[i] - __bfloat162float(h));
        h = __float2bfloat16(acck[i]);
        g_khi[which][(size_t)n * D + c] = h;
        g_klo[which][(size_t)n * D + c] = __float2bfloat16(acck[i] - __bfloat162float(h));
    }
    // V splits, coalesced bf16x2 writes
    uint32_t* vh = (uint32_t*)g_vhi[which];
    uint32_t* vl = (uint32_t*)g_vlo[which];
    for (int u = tid; u < 1024; u += 256) {
        int r = u >> 5, cc = (u & 31) * 2;
        float v0 = sIn[r][cc], v1 = sIn[r][cc + 1];
        uint32_t h = pack_bf16x2(v0, v1);
        size_t idx = ((size_t)(row0 + r) * D + cc) >> 1;
        vh[idx] = h;
        vl[idx] = pack_bf16x2(v0 - lo_bf16(h), v1 - hi_bf16(h));
    }
}

// ---------------------------------------------------------------------------
// kernel 2: single-pass flash attention, depth-3 cp.async ring, 1 barrier/iter
// CTA: 128 threads (4 warps), 64 query rows, 64-key tiles, 2 CTAs/SM.
// (Round-7 proven shape: 2 CTAs/SM gives phase overlap MMA<->softmax.)
// ---------------------------------------------------------------------------
#define TILE_B 36864   // per-buffer: 4 arrays x 64 rows x 144B
#define OFF_KH 0
#define OFF_KL 9216
#define OFF_VH 18432
#define OFF_VL 27648
#define SMEM_FLASH (3 * TILE_B)

__device__ __forceinline__ void flash_issue_tile(uint32_t sbu, int buf,
                                                 int which, int j0, int tid) {
    uint32_t bo = sbu + (uint32_t)buf * TILE_B;
#pragma unroll
    for (int u = tid; u < 512; u += 128) {
        int r = u >> 3, ch = u & 7;
        uint32_t so = (uint32_t)r * RB + (uint32_t)ch * 16;
        cp16(bo + OFF_KH + so, g_khi[which] + (size_t)(j0 + r) * D + ch * 8);
        cp16(bo + OFF_KL + so, g_klo[which] + (size_t)(j0 + r) * D + ch * 8);
        cp16(bo + OFF_VH + so, g_vhi[which] + (size_t)(j0 + r) * D + ch * 8);
        cp16(bo + OFF_VL + so, g_vlo[which] + (size_t)(j0 + r) * D + ch * 8);
    }
    CP_COMMIT();
}

__global__ __launch_bounds__(128, 2) void flash_mma_kernel() {
    extern __shared__ char smf[];
    uint32_t sbu = smem_u32(smf);

    int tid = threadIdx.x;
    int w = tid >> 5, lane = tid & 31;
    int q = lane >> 2, c = lane & 3;
    int which = blockIdx.x >> 7;
    int q0 = (blockIdx.x & 127) * 64;
    int rowA = w * 16 + q;

    // stage Q tile into buf0 (plain loads), extract A fragments
    for (int u = tid; u < 512; u += 128) {
        int r = u >> 3, ch = u & 7;
        *(uint4*)(smf + OFF_KH + r * RB + ch * 16) =
            ((const uint4*)(g_qhi[which] + (size_t)(q0 + r) * D))[ch];
        *(uint4*)(smf + OFF_KL + r * RB + ch * 16) =
            ((const uint4*)(g_qlo[which] + (size_t)(q0 + r) * D))[ch];
    }
    __syncthreads();

    uint32_t aq[2][4][4];
    {
        const uint32_t* ph = (const uint32_t*)(smf + OFF_KH);
        const uint32_t* pl = (const uint32_t*)(smf + OFF_KL);
#pragma unroll
        for (int kk = 0; kk < 4; kk++) {
            int col = kk * 8 + c;
            aq[0][kk][0] = ph[rowA * LS32 + col];
            aq[0][kk][1] = ph[(rowA + 8) * LS32 + col];
            aq[0][kk][2] = ph[rowA * LS32 + col + 4];
            aq[0][kk][3] = ph[(rowA + 8) * LS32 + col + 4];
            aq[1][kk][0] = pl[rowA * LS32 + col];
            aq[1][kk][1] = pl[(rowA + 8) * LS32 + col];
            aq[1][kk][2] = pl[rowA * LS32 + col + 4];
            aq[1][kk][3] = pl[(rowA + 8) * LS32 + col + 4];
        }
    }
    __syncthreads();

    // prologue: prefetch tiles 0 and 1
    flash_issue_tile(sbu, 0, which, 0, tid);
    flash_issue_tile(sbu, 1, which, 64, tid);

    float o[8][4] = {};
    float m0 = -INFINITY, m1 = -INFINITY, l0 = 0.f, l1 = 0.f;
    uint32_t lmoff = (uint32_t)(lane & 7) * RB + (uint32_t)(lane >> 3) * 16;

    int bi = 0, bi2 = 2;   // current buffer, prefetch buffer
    for (int t = 0; t < 128; t++) {
        if (t < 126) cp_wait<1>(); else cp_wait<0>();
        __syncthreads();
        if (t + 2 < 128) flash_issue_tile(sbu, bi2, which, (t + 2) * 64, tid);
        uint32_t bufb = sbu + (uint32_t)bi * TILE_B;
        bi = (bi == 2) ? 0 : bi + 1;
        bi2 = (bi2 == 2) ? 0 : bi2 + 1;

        // ---- S = Q K^T (3 split passes: hh, hl, lh) ----
        float sc[8][4] = {};
#pragma unroll
        for (int nt = 0; nt < 8; nt++) {
            uint32_t a0 = bufb + (uint32_t)nt * (8 * RB) + lmoff;
            uint32_t bh[4][2], bl[4][2];
            ldmx4(&bh[0][0], a0 + OFF_KH);
            ldmx4(&bh[2][0], a0 + OFF_KH + 64);
            ldmx4(&bl[0][0], a0 + OFF_KL);
            ldmx4(&bl[2][0], a0 + OFF_KL + 64);
#pragma unroll
            for (int kk = 0; kk < 4; kk++) mma16816(sc[nt], aq[0][kk], bh[kk]);
#pragma unroll
            for (int kk = 0; kk < 4; kk++) mma16816(sc[nt], aq[0][kk], bl[kk]);
#pragma unroll
            for (int kk = 0; kk < 4; kk++) mma16816(sc[nt], aq[1][kk], bh[kk]);
        }

        // ---- online softmax ----
        float mx0 = -INFINITY, mx1 = -INFINITY;
#pragma unroll
        for (int nt = 0; nt < 8; nt++) {
            mx0 = fmaxf(mx0, fmaxf(sc[nt][0], sc[nt][1]));
            mx1 = fmaxf(mx1, fmaxf(sc[nt][2], sc[nt][3]));
        }
        mx0 = fmaxf(mx0, __shfl_xor_sync(0xffffffffu, mx0, 1));
        mx0 = fmaxf(mx0, __shfl_xor_sync(0xffffffffu, mx0, 2));
        mx1 = fmaxf(mx1, __shfl_xor_sync(0xffffffffu, mx1, 1));
        mx1 = fmaxf(mx1, __shfl_xor_sync(0xffffffffu, mx1, 2));
        float m0n = fmaxf(m0, mx0), m1n = fmaxf(m1, mx1);
        float f0 = __expf(SCALE * (m0 - m0n));
        float f1 = __expf(SCALE * (m1 - m1n));
        m0 = m0n; m1 = m1n;
        l0 *= f0; l1 *= f1;

        uint32_t pah[8], pbh[8], pal[8], pbl[8];
#pragma unroll
        for (int nt = 0; nt < 8; nt++) {
            float p0 = __expf(SCALE * (sc[nt][0] - m0));
            float p1 = __expf(SCALE * (sc[nt][1] - m0));
            float p2 = __expf(SCALE * (sc[nt][2] - m1));
            float p3 = __expf(SCALE * (sc[nt][3] - m1));
            l0 += p0 + p1; l1 += p2 + p3;
            uint32_t h = pack_bf16x2(p0, p1);
            pah[nt] = h;
            pal[nt] = pack_bf16x2(p0 - lo_bf16(h), p1 - hi_bf16(h));
            h = pack_bf16x2(p2, p3);
            pbh[nt] = h;
            pbl[nt] = pack_bf16x2(p2 - lo_bf16(h), p3 - hi_bf16(h));
            o[nt][0] *= f0; o[nt][1] *= f0; o[nt][2] *= f1; o[nt][3] *= f1;
        }

        // ---- O += P V (3 split passes), row-major V via ldmatrix.trans ----
#pragma unroll
        for (int nt = 0; nt < 8; nt++) {
            uint32_t av = bufb + OFF_VH + (uint32_t)lane * RB + (uint32_t)nt * 16;
            uint32_t vbh[4][2], vbl[4][2];
            ldmx4t(&vbh[0][0], av);
            ldmx4t(&vbh[2][0], av + 32 * RB);
            ldmx4t(&vbl[0][0], av + (OFF_VL - OFF_VH));
            ldmx4t(&vbl[2][0], av + (OFF_VL - OFF_VH) + 32 * RB);
#pragma unroll
            for (int kk = 0; kk < 4; kk++) {
                uint32_t Ah[4] = {pah[2 * kk], pbh[2 * kk], pah[2 * kk + 1], pbh[2 * kk + 1]};
                uint32_t Al[4] = {pal[2 * kk], pbl[2 * kk], pal[2 * kk + 1], pbl[2 * kk + 1]};
                mma16816(o[nt], Ah, vbh[kk]);
                mma16816(o[nt], Ah, vbl[kk]);
                mma16816(o[nt], Al, vbh[kk]);
            }
        }
    }

    // ---- epilogue ----
    l0 += __shfl_xor_sync(0xffffffffu, l0, 1);
    l0 += __shfl_xor_sync(0xffffffffu, l0, 2);
    l1 += __shfl_xor_sync(0xffffffffu, l1, 1);
    l1 += __shfl_xor_sync(0xffffffffu, l1, 2);
    float inv0 = 1.0f / l0, inv1 = 1.0f / l1;
    float n0 = 0.f, n1 = 0.f;
    int row = q0 + rowA;
    uint32_t* dh = (uint32_t*)g_atthi[which];
    uint32_t* dl = (uint32_t*)g_attlo[which];
#pragma unroll
    for (int nt = 0; nt < 8; nt++) {
        float o0 = o[nt][0] * inv0, o1 = o[nt][1] * inv0;
        float o2 = o[nt][2] * inv1, o3 = o[nt][3] * inv1;
        n0 = fmaf(o0, o0, fmaf(o1, o1, n0));
        n1 = fmaf(o2, o2, fmaf(o3, o3, n1));
        uint32_t h = pack_bf16x2(o0, o1);
        dh[(size_t)row * 32 + nt * 4 + c] = h;
        dl[(size_t)row * 32 + nt * 4 + c] = pack_bf16x2(o0 - lo_bf16(h), o1 - hi_bf16(h));
        h = pack_bf16x2(o2, o3);
        dh[(size_t)(row + 8) * 32 + nt * 4 + c] = h;
        dl[(size_t)(row + 8) * 32 + nt * 4 + c] = pack_bf16x2(o2 - lo_bf16(h), o3 - hi_bf16(h));
    }
    n0 += __shfl_xor_sync(0xffffffffu, n0, 1);
    n0 += __shfl_xor_sync(0xffffffffu, n0, 2);
    n1 += __shfl_xor_sync(0xffffffffu, n1, 1);
    n1 += __shfl_xor_sync(0xffffffffu, n1, 2);
    if (c == 0) {
        g_norm2[which][row] = n0;
        g_norm2[which][row + 8] = n1;
    }
}

// ---------------------------------------------------------------------------
// kernel 3: pairwise RBF via mma.sync (64x64 tile, 3-pass split, 3 CTAs/SM)
// ---------------------------------------------------------------------------
__global__ __launch_bounds__(128, 3) void pairwise_mma_kernel(float* __restrict__ out) {
    __shared__ __nv_bfloat16 sAh[64 * LSTRIDE];
    __shared__ __nv_bfloat16 sAl[64 * LSTRIDE];
    __shared__ __nv_bfloat16 sBh[64 * LSTRIDE];
    __shared__ __nv_bfloat16 sBl[64 * LSTRIDE];
    __shared__ float syn[64];

    int tid = threadIdx.x;
    int w = tid >> 5, lane = tid & 31;
    int q = lane >> 2, c = lane & 3;
    int m0 = blockIdx.y * 64;
    int j0 = blockIdx.x * 64;
    int rowA = w * 16 + q;

    for (int u = tid; u < 512; u += 128) {
        int r = u >> 3, ch = u & 7;
        ((uint4*)(sAh + r * LSTRIDE))[ch] = ((const uint4*)(g_atthi[0] + (size_t)(m0 + r) * D))[ch];
        ((uint4*)(sAl + r * LSTRIDE))[ch] = ((const uint4*)(g_attlo[0] + (size_t)(m0 + r) * D))[ch];
        ((uint4*)(sBh + r * LSTRIDE))[ch] = ((const uint4*)(g_atthi[1] + (size_t)(j0 + r) * D))[ch];
        ((uint4*)(sBl + r * LSTRIDE))[ch] = ((const uint4*)(g_attlo[1] + (size_t)(j0 + r) * D))[ch];
    }
    if (tid < 64) syn[tid] = g_norm2[1][j0 + tid];
    __syncthreads();

    uint32_t aq[2][4][4];
    {
        const uint32_t* ph = (const uint32_t*)sAh;
        const uint32_t* pl = (const uint32_t*)sAl;
#pragma unroll
        for (int kk = 0; kk < 4; kk++) {
            int col = kk * 8 + c;
            aq[0][kk][0] = ph[rowA * LS32 + col];
            aq[0][kk][1] = ph[(rowA + 8) * LS32 + col];
            aq[0][kk][2] = ph[rowA * LS32 + col + 4];
            aq[0][kk][3] = ph[(rowA + 8) * LS32 + col + 4];
            aq[1][kk][0] = pl[rowA * LS32 + col];
            aq[1][kk][1] = pl[(rowA + 8) * LS32 + col];
            aq[1][kk][2] = pl[rowA * LS32 + col + 4];
            aq[1][kk][3] = pl[(rowA + 8) * LS32 + col + 4];
        }
    }

    uint32_t sbh = smem_u32(sBh), sbl = smem_u32(sBl);
    uint32_t lmoff = (uint32_t)(lane & 7) * RB + (uint32_t)(lane >> 3) * 16;
    float acc[8][4] = {};
#pragma unroll
    for (int nt = 0; nt < 8; nt++) {
        uint32_t ro = (uint32_t)nt * (8 * RB) + lmoff;
        uint32_t bh[4][2], bl[4][2];
        ldmx4(&bh[0][0], sbh + ro);
        ldmx4(&bh[2][0], sbh + ro + 64);
        ldmx4(&bl[0][0], sbl + ro);
        ldmx4(&bl[2][0], sbl + ro + 64);
#pragma unroll
        for (int kk = 0; kk < 4; kk++) mma16816(acc[nt], aq[0][kk], bh[kk]);
#pragma unroll
        for (int kk = 0; kk < 4; kk++) mma16816(acc[nt], aq[0][kk], bl[kk]);
#pragma unroll
        for (int kk = 0; kk < 4; kk++) mma16816(acc[nt], aq[1][kk], bh[kk]);
    }

    int rowx = m0 + rowA;
    float xn0 = g_norm2[0][rowx];
    float xn1 = g_norm2[0][rowx + 8];
#pragma unroll
    for (int nt = 0; nt < 8; nt++) {
        int cb = nt * 8 + 2 * c;
        float y0 = syn[cb], y1 = syn[cb + 1];
        float2 e;
        e.x = __expf(-(xn0 + y0 - 2.f * acc[nt][0]));
        e.y = __expf(-(xn0 + y1 - 2.f * acc[nt][1]));
        *reinterpret_cast<float2*>(out + (size_t)rowx * N + j0 + cb) = e;
        e.x = __expf(-(xn1 + y0 - 2.f * acc[nt][2]));
        e.y = __expf(-(xn1 + y1 - 2.f * acc[nt][3]));
        *reinterpret_cast<float2*>(out + (size_t)(rowx + 8) * N + j0 + cb) = e;
    }
}

// ---------------------------------------------------------------------------
extern "C" void kernel_launch(void* const* d_in, const int* in_sizes, int n_in,
                              void* d_out, int out_size) {
    const float* Wq = (const float*)d_in[0];
    const float* Wk = (const float*)d_in[1];
    const float* x  = (const float*)d_in[2];
    const float* y  = (const float*)d_in[3];
    float* out = (float*)d_out;

    prep_kernel<<<512, 256>>>(x, y, Wq, Wk);

    cudaFuncSetAttribute(flash_mma_kernel, cudaFuncAttributeMaxDynamicSharedMemorySize,
                         SMEM_FLASH);
    flash_mma_kernel<<<256, 128, SMEM_FLASH>>>();

    dim3 grid(N / 64, N / 64);
    pairwise_mma_kernel<<<grid, 128>>>(out);
}

// round 15
// speedup vs baseline: 1.0934x; 1.0266x over previous
#include <cuda_runtime.h>
#include <cuda_bf16.h>
#include <cstdint>
#include <math.h>

#define N 8192
#define D 64
#define SCALE 0.125f      // 1/sqrt(64)
#define LSTRIDE 72        // smem row stride in bf16 (144B, conflict-free)
#define LS32 36           // row stride in u32 words
#define RB 144            // row stride in bytes
#define L2E 1.44269504f
#define CEXP 0.18033688f  // SCALE * log2(e)

// ---------------------------------------------------------------------------
// global scratch (no allocation allowed) -- all row-major [n][64] bf16 splits
// ---------------------------------------------------------------------------
__device__ __nv_bfloat16 g_qhi[2][N * D];
__device__ __nv_bfloat16 g_qlo[2][N * D];
__device__ __nv_bfloat16 g_khi[2][N * D];
__device__ __nv_bfloat16 g_klo[2][N * D];
__device__ __nv_bfloat16 g_vhi[2][N * D];    // V (inputs) split, row-major
__device__ __nv_bfloat16 g_vlo[2][N * D];
__device__ __nv_bfloat16 g_atthi[2][N * D];
__device__ __nv_bfloat16 g_attlo[2][N * D];
__device__ float g_norm2[2][N];

// ---------------------------------------------------------------------------
// helpers
// ---------------------------------------------------------------------------
__device__ __forceinline__ uint32_t smem_u32(const void* p) {
    uint32_t a;
    asm("{ .reg .u64 t; cvta.to.shared.u64 t, %1; cvt.u32.u64 %0, t; }" : "=r"(a) : "l"(p));
    return a;
}
__device__ __forceinline__ void mma16816(float* c, const uint32_t* a, const uint32_t* b) {
    asm volatile(
        "mma.sync.aligned.m16n8k16.row.col.f32.bf16.bf16.f32 "
        "{%0,%1,%2,%3}, {%4,%5,%6,%7}, {%8,%9}, {%0,%1,%2,%3};\n"
        : "+f"(c[0]), "+f"(c[1]), "+f"(c[2]), "+f"(c[3])
        : "r"(a[0]), "r"(a[1]), "r"(a[2]), "r"(a[3]), "r"(b[0]), "r"(b[1]));
}
__device__ __forceinline__ void ldmx4(uint32_t* r, uint32_t saddr) {
    asm volatile("ldmatrix.sync.aligned.m8n8.x4.shared.b16 {%0,%1,%2,%3}, [%4];"
        : "=r"(r[0]), "=r"(r[1]), "=r"(r[2]), "=r"(r[3]) : "r"(saddr));
}
__device__ __forceinline__ void ldmx4t(uint32_t* r, uint32_t saddr) {
    asm volatile("ldmatrix.sync.aligned.m8n8.x4.trans.shared.b16 {%0,%1,%2,%3}, [%4];"
        : "=r"(r[0]), "=r"(r[1]), "=r"(r[2]), "=r"(r[3]) : "r"(saddr));
}
__device__ __forceinline__ void cp16(uint32_t saddr, const void* gaddr) {
    asm volatile("cp.async.cg.shared.global [%0], [%1], 16;" :: "r"(saddr), "l"(gaddr));
}
#define CP_COMMIT() asm volatile("cp.async.commit_group;" ::: "memory")
template <int n>
__device__ __forceinline__ void cp_wait() {
    asm volatile("cp.async.wait_group %0;" :: "n"(n) : "memory");
}
__device__ __forceinline__ uint32_t pack_bf16x2(float lo, float hi) {
    uint32_t r;
    asm("cvt.rn.bf16x2.f32 %0, %1, %2;" : "=r"(r) : "f"(hi), "f"(lo));
    return r;
}
__device__ __forceinline__ float lo_bf16(uint32_t p) { return __uint_as_float(p << 16); }
__device__ __forceinline__ float hi_bf16(uint32_t p) { return __uint_as_float(p & 0xFFFF0000u); }
__device__ __forceinline__ float ex2(float x) {
    float r;
    asm("ex2.approx.f32 %0, %1;" : "=f"(r) : "f"(x));
    return r;
}

// ---------------------------------------------------------------------------
// kernel 1: Q/K projection + bf16 splits. 512 blocks x 32 rows. (proven: 23us)
// ---------------------------------------------------------------------------
__global__ __launch_bounds__(256) void prep_kernel(const float* __restrict__ x,
                                                   const float* __restrict__ y,
                                                   const float* __restrict__ Wq,
                                                   const float* __restrict__ Wk) {
    __shared__ float sW[2][D * D];   // 32KB
    __shared__ float sIn[32][D];     // 8KB
    int tid = threadIdx.x;
    int b = blockIdx.x;
    int which = (b >= 256) ? 1 : 0;
    const float* in = which ? y : x;
    int row0 = (b & 255) * 32;

    for (int i = tid; i < D * D; i += 256) { sW[0][i] = Wq[i]; sW[1][i] = Wk[i]; }
    for (int u = tid; u < 32 * D; u += 256)
        ((float*)sIn)[u] = in[(size_t)row0 * D + u];
    __syncthreads();

    int c = tid & 63;
    int rg = tid >> 6;
    float accq[8] = {}, acck[8] = {};
#pragma unroll
    for (int k = 0; k < D; k++) {
        float wq = sW[0][k * D + c];
        float wk = sW[1][k * D + c];
#pragma unroll
        for (int i = 0; i < 8; i++) {
            float v = sIn[rg * 8 + i][k];
            accq[i] = fmaf(v, wq, accq[i]);
            acck[i] = fmaf(v, wk, acck[i]);
        }
    }
#pragma unroll
    for (int i = 0; i < 8; i++) {
        int n = row0 + rg * 8 + i;
        __nv_bfloat16 h;
        h = __float2bfloat16(accq[i]);
        g_qhi[which][(size_t)n * D + c] = h;
        g_qlo[which][(size_t)n * D + c] = __float2bfloat16(accq[i] - __bfloat162float(h));
        h = __float2bfloat16(acck[i]);
        g_khi[which][(size_t)n * D + c] = h;
        g_klo[which][(size_t)n * D + c] = __float2bfloat16(acck[i] - __bfloat162float(h));
    }
    uint32_t* vh = (uint32_t*)g_vhi[which];
    uint32_t* vl = (uint32_t*)g_vlo[which];
    for (int u = tid; u < 1024; u += 256) {
        int r = u >> 5, cc = (u & 31) * 2;
        float v0 = sIn[r][cc], v1 = sIn[r][cc + 1];
        uint32_t h = pack_bf16x2(v0, v1);
        size_t idx = ((size_t)(row0 + r) * D + cc) >> 1;
        vh[idx] = h;
        vl[idx] = pack_bf16x2(v0 - lo_bf16(h), v1 - hi_bf16(h));
    }
}

// ---------------------------------------------------------------------------
// kernel 2: single-pass flash attention, depth-3 cp.async ring, 1 barrier/iter
// CTA: 128 threads (4 warps), 64 query rows, 2 CTAs/SM. (round-10 proven)
// ---------------------------------------------------------------------------
#define TILE_B 36864
#define OFF_KH 0
#define OFF_KL 9216
#define OFF_VH 18432
#define OFF_VL 27648
#define SMEM_FLASH (3 * TILE_B)

__device__ __forceinline__ void flash_issue_tile(uint32_t sbu, int buf,
                                                 int which, int j0, int tid) {
    uint32_t bo = sbu + (uint32_t)buf * TILE_B;
#pragma unroll
    for (int u = tid; u < 512; u += 128) {
        int r = u >> 3, ch = u & 7;
        uint32_t so = (uint32_t)r * RB + (uint32_t)ch * 16;
        cp16(bo + OFF_KH + so, g_khi[which] + (size_t)(j0 + r) * D + ch * 8);
        cp16(bo + OFF_KL + so, g_klo[which] + (size_t)(j0 + r) * D + ch * 8);
        cp16(bo + OFF_VH + so, g_vhi[which] + (size_t)(j0 + r) * D + ch * 8);
        cp16(bo + OFF_VL + so, g_vlo[which] + (size_t)(j0 + r) * D + ch * 8);
    }
    CP_COMMIT();
}

__global__ __launch_bounds__(128, 2) void flash_mma_kernel() {
    extern __shared__ char smf[];
    uint32_t sbu = smem_u32(smf);

    int tid = threadIdx.x;
    int w = tid >> 5, lane = tid & 31;
    int q = lane >> 2, c = lane & 3;
    int which = blockIdx.x >> 7;
    int q0 = (blockIdx.x & 127) * 64;
    int rowA = w * 16 + q;

    for (int u = tid; u < 512; u += 128) {
        int r = u >> 3, ch = u & 7;
        *(uint4*)(smf + OFF_KH + r * RB + ch * 16) =
            ((const uint4*)(g_qhi[which] + (size_t)(q0 + r) * D))[ch];
        *(uint4*)(smf + OFF_KL + r * RB + ch * 16) =
            ((const uint4*)(g_qlo[which] + (size_t)(q0 + r) * D))[ch];
    }
    __syncthreads();

    uint32_t aq[2][4][4];
    {
        const uint32_t* ph = (const uint32_t*)(smf + OFF_KH);
        const uint32_t* pl = (const uint32_t*)(smf + OFF_KL);
#pragma unroll
        for (int kk = 0; kk < 4; kk++) {
            int col = kk * 8 + c;
            aq[0][kk][0] = ph[rowA * LS32 + col];
            aq[0][kk][1] = ph[(rowA + 8) * LS32 + col];
            aq[0][kk][2] = ph[rowA * LS32 + col + 4];
            aq[0][kk][3] = ph[(rowA + 8) * LS32 + col + 4];
            aq[1][kk][0] = pl[rowA * LS32 + col];
            aq[1][kk][1] = pl[(rowA + 8) * LS32 + col];
            aq[1][kk][2] = pl[rowA * LS32 + col + 4];
            aq[1][kk][3] = pl[(rowA + 8) * LS32 + col + 4];
        }
    }
    __syncthreads();

    flash_issue_tile(sbu, 0, which, 0, tid);
    flash_issue_tile(sbu, 1, which, 64, tid);

    float o[8][4] = {};
    float m0 = -INFINITY, m1 = -INFINITY;
    float l0a = 0.f, l0b = 0.f, l1a = 0.f, l1b = 0.f;
    uint32_t lmoff = (uint32_t)(lane & 7) * RB + (uint32_t)(lane >> 3) * 16;

    int bi = 0, bi2 = 2;
    for (int t = 0; t < 128; t++) {
        if (t < 126) cp_wait<1>(); else cp_wait<0>();
        __syncthreads();
        if (t + 2 < 128) flash_issue_tile(sbu, bi2, which, (t + 2) * 64, tid);
        uint32_t bufb = sbu + (uint32_t)bi * TILE_B;
        bi = (bi == 2) ? 0 : bi + 1;
        bi2 = (bi2 == 2) ? 0 : bi2 + 1;

        // ---- S = Q K^T (3 split passes: hh, hl, lh) ----
        float sc[8][4] = {};
#pragma unroll
        for (int nt = 0; nt < 8; nt++) {
            uint32_t a0 = bufb + (uint32_t)nt * (8 * RB) + lmoff;
            uint32_t bh[4][2], bl[4][2];
            ldmx4(&bh[0][0], a0 + OFF_KH);
            ldmx4(&bh[2][0], a0 + OFF_KH + 64);
            ldmx4(&bl[0][0], a0 + OFF_KL);
            ldmx4(&bl[2][0], a0 + OFF_KL + 64);
#pragma unroll
            for (int kk = 0; kk < 4; kk++) mma16816(sc[nt], aq[0][kk], bh[kk]);
#pragma unroll
            for (int kk = 0; kk < 4; kk++) mma16816(sc[nt], aq[0][kk], bl[kk]);
#pragma unroll
            for (int kk = 0; kk < 4; kk++) mma16816(sc[nt], aq[1][kk], bh[kk]);
        }

        // ---- online softmax (ex2-based: exp(SCALE*(s-m)) = ex2(fma(s,C,-m*C))) ----
        float mx0 = -INFINITY, mx1 = -INFINITY;
#pragma unroll
        for (int nt = 0; nt < 8; nt++) {
            mx0 = fmaxf(mx0, fmaxf(sc[nt][0], sc[nt][1]));
            mx1 = fmaxf(mx1, fmaxf(sc[nt][2], sc[nt][3]));
        }
        mx0 = fmaxf(mx0, __shfl_xor_sync(0xffffffffu, mx0, 1));
        mx0 = fmaxf(mx0, __shfl_xor_sync(0xffffffffu, mx0, 2));
        mx1 = fmaxf(mx1, __shfl_xor_sync(0xffffffffu, mx1, 1));
        mx1 = fmaxf(mx1, __shfl_xor_sync(0xffffffffu, mx1, 2));
        float m0n = fmaxf(m0, mx0), m1n = fmaxf(m1, mx1);
        float f0 = ex2((m0 - m0n) * CEXP);
        float f1 = ex2((m1 - m1n) * CEXP);
        m0 = m0n; m1 = m1n;
        float nmc0 = -m0n * CEXP, nmc1 = -m1n * CEXP;
        l0a *= f0; l0b *= f0; l1a *= f1; l1b *= f1;

        uint32_t pah[8], pbh[8], pal[8], pbl[8];
#pragma unroll
        for (int nt = 0; nt < 8; nt++) {
            float p0 = ex2(fmaf(sc[nt][0], CEXP, nmc0));
            float p1 = ex2(fmaf(sc[nt][1], CEXP, nmc0));
            float p2 = ex2(fmaf(sc[nt][2], CEXP, nmc1));
            float p3 = ex2(fmaf(sc[nt][3], CEXP, nmc1));
            l0a += p0; l0b += p1; l1a += p2; l1b += p3;
            uint32_t h = pack_bf16x2(p0, p1);
            pah[nt] = h;
            pal[nt] = pack_bf16x2(p0 - lo_bf16(h), p1 - hi_bf16(h));
            h = pack_bf16x2(p2, p3);
            pbh[nt] = h;
            pbl[nt] = pack_bf16x2(p2 - lo_bf16(h), p3 - hi_bf16(h));
            o[nt][0] *= f0; o[nt][1] *= f0; o[nt][2] *= f1; o[nt][3] *= f1;
        }

        // ---- O += P V (3 split passes), row-major V via ldmatrix.trans ----
#pragma unroll
        for (int nt = 0; nt < 8; nt++) {
            uint32_t av = bufb + OFF_VH + (uint32_t)lane * RB + (uint32_t)nt * 16;
            uint32_t vbh[4][2], vbl[4][2];
            ldmx4t(&vbh[0][0], av);
            ldmx4t(&vbh[2][0], av + 32 * RB);
            ldmx4t(&vbl[0][0], av + (OFF_VL - OFF_VH));
            ldmx4t(&vbl[2][0], av + (OFF_VL - OFF_VH) + 32 * RB);
#pragma unroll
            for (int kk = 0; kk < 4; kk++) {
                uint32_t Ah[4] = {pah[2 * kk], pbh[2 * kk], pah[2 * kk + 1], pbh[2 * kk + 1]};
                uint32_t Al[4] = {pal[2 * kk], pbl[2 * kk], pal[2 * kk + 1], pbl[2 * kk + 1]};
                mma16816(o[nt], Ah, vbh[kk]);
                mma16816(o[nt], Ah, vbl[kk]);
                mma16816(o[nt], Al, vbh[kk]);
            }
        }
    }

    // ---- epilogue ----
    float l0 = l0a + l0b, l1 = l1a + l1b;
    l0 += __shfl_xor_sync(0xffffffffu, l0, 1);
    l0 += __shfl_xor_sync(0xffffffffu, l0, 2);
    l1 += __shfl_xor_sync(0xffffffffu, l1, 1);
    l1 += __shfl_xor_sync(0xffffffffu, l1, 2);
    float inv0 = 1.0f / l0, inv1 = 1.0f / l1;
    float n0 = 0.f, n1 = 0.f;
    int row = q0 + rowA;
    uint32_t* dh = (uint32_t*)g_atthi[which];
    uint32_t* dl = (uint32_t*)g_attlo[which];
#pragma unroll
    for (int nt = 0; nt < 8; nt++) {
        float o0 = o[nt][0] * inv0, o1 = o[nt][1] * inv0;
        float o2 = o[nt][2] * inv1, o3 = o[nt][3] * inv1;
        n0 = fmaf(o0, o0, fmaf(o1, o1, n0));
        n1 = fmaf(o2, o2, fmaf(o3, o3, n1));
        uint32_t h = pack_bf16x2(o0, o1);
        dh[(size_t)row * 32 + nt * 4 + c] = h;
        dl[(size_t)row * 32 + nt * 4 + c] = pack_bf16x2(o0 - lo_bf16(h), o1 - hi_bf16(h));
        h = pack_bf16x2(o2, o3);
        dh[(size_t)(row + 8) * 32 + nt * 4 + c] = h;
        dl[(size_t)(row + 8) * 32 + nt * 4 + c] = pack_bf16x2(o2 - lo_bf16(h), o3 - hi_bf16(h));
    }
    n0 += __shfl_xor_sync(0xffffffffu, n0, 1);
    n0 += __shfl_xor_sync(0xffffffffu, n0, 2);
    n1 += __shfl_xor_sync(0xffffffffu, n1, 1);
    n1 += __shfl_xor_sync(0xffffffffu, n1, 2);
    if (c == 0) {
        g_norm2[which][row] = n0;
        g_norm2[which][row + 8] = n1;
    }
}

// ---------------------------------------------------------------------------
// kernel 3: pairwise RBF via mma.sync (64x64 tile, 3-pass split, 3 CTAs/SM)
// EXACT round-10 structure; only the epilogue exp is ex2-based.
// ---------------------------------------------------------------------------
__global__ __launch_bounds__(128, 3) void pairwise_mma_kernel(float* __restrict__ out) {
    __shared__ __nv_bfloat16 sAh[64 * LSTRIDE];
    __shared__ __nv_bfloat16 sAl[64 * LSTRIDE];
    __shared__ __nv_bfloat16 sBh[64 * LSTRIDE];
    __shared__ __nv_bfloat16 sBl[64 * LSTRIDE];
    __shared__ float syn[64];

    int tid = threadIdx.x;
    int w = tid >> 5, lane = tid & 31;
    int q = lane >> 2, c = lane & 3;
    int m0 = blockIdx.y * 64;
    int j0 = blockIdx.x * 64;
    int rowA = w * 16 + q;

    for (int u = tid; u < 512; u += 128) {
        int r = u >> 3, ch = u & 7;
        ((uint4*)(sAh + r * LSTRIDE))[ch] = ((const uint4*)(g_atthi[0] + (size_t)(m0 + r) * D))[ch];
        ((uint4*)(sAl + r * LSTRIDE))[ch] = ((const uint4*)(g_attlo[0] + (size_t)(m0 + r) * D))[ch];
        ((uint4*)(sBh + r * LSTRIDE))[ch] = ((const uint4*)(g_atthi[1] + (size_t)(j0 + r) * D))[ch];
        ((uint4*)(sBl + r * LSTRIDE))[ch] = ((const uint4*)(g_attlo[1] + (size_t)(j0 + r) * D))[ch];
    }
    if (tid < 64) syn[tid] = g_norm2[1][j0 + tid] * L2E;
    __syncthreads();

    uint32_t aq[2][4][4];
    {
        const uint32_t* ph = (const uint32_t*)sAh;
        const uint32_t* pl = (const uint32_t*)sAl;
#pragma unroll
        for (int kk = 0; kk < 4; kk++) {
            int col = kk * 8 + c;
            aq[0][kk][0] = ph[rowA * LS32 + col];
            aq[0][kk][1] = ph[(rowA + 8) * LS32 + col];
            aq[0][kk][2] = ph[rowA * LS32 + col + 4];
            aq[0][kk][3] = ph[(rowA + 8) * LS32 + col + 4];
            aq[1][kk][0] = pl[rowA * LS32 + col];
            aq[1][kk][1] = pl[(rowA + 8) * LS32 + col];
            aq[1][kk][2] = pl[rowA * LS32 + col + 4];
            aq[1][kk][3] = pl[(rowA + 8) * LS32 + col + 4];
        }
    }

    uint32_t sbh = smem_u32(sBh), sbl = smem_u32(sBl);
    uint32_t lmoff = (uint32_t)(lane & 7) * RB + (uint32_t)(lane >> 3) * 16;
    float acc[8][4] = {};
#pragma unroll
    for (int nt = 0; nt < 8; nt++) {
        uint32_t ro = (uint32_t)nt * (8 * RB) + lmoff;
        uint32_t bh[4][2], bl[4][2];
        ldmx4(&bh[0][0], sbh + ro);
        ldmx4(&bh[2][0], sbh + ro + 64);
        ldmx4(&bl[0][0], sbl + ro);
        ldmx4(&bl[2][0], sbl + ro + 64);
#pragma unroll
        for (int kk = 0; kk < 4; kk++) mma16816(acc[nt], aq[0][kk], bh[kk]);
#pragma unroll
        for (int kk = 0; kk < 4; kk++) mma16816(acc[nt], aq[0][kk], bl[kk]);
#pragma unroll
        for (int kk = 0; kk < 4; kk++) mma16816(acc[nt], aq[1][kk], bh[kk]);
    }

    int rowx = m0 + rowA;
    float xnL0 = g_norm2[0][rowx] * L2E;
    float xnL1 = g_norm2[0][rowx + 8] * L2E;
    const float TWOC = 2.0f * L2E;
#pragma unroll
    for (int nt = 0; nt < 8; nt++) {
        int cb = nt * 8 + 2 * c;
        float y0 = syn[cb], y1 = syn[cb + 1];
        float2 e;
        e.x = ex2(fmaf(acc[nt][0], TWOC, -(xnL0 + y0)));
        e.y = ex2(fmaf(acc[nt][1], TWOC, -(xnL0 + y1)));
        *reinterpret_cast<float2*>(out + (size_t)rowx * N + j0 + cb) = e;
        e.x = ex2(fmaf(acc[nt][2], TWOC, -(xnL1 + y0)));
        e.y = ex2(fmaf(acc[nt][3], TWOC, -(xnL1 + y1)));
        *reinterpret_cast<float2*>(out + (size_t)(rowx + 8) * N + j0 + cb) = e;
    }
}

// ---------------------------------------------------------------------------
extern "C" void kernel_launch(void* const* d_in, const int* in_sizes, int n_in,
                              void* d_out, int out_size) {
    const float* Wq = (const float*)d_in[0];
    const float* Wk = (const float*)d_in[1];
    const float* x  = (const float*)d_in[2];
    const float* y  = (const float*)d_in[3];
    float* out = (float*)d_out;

    prep_kernel<<<512, 256>>>(x, y, Wq, Wk);

    cudaFuncSetAttribute(flash_mma_kernel, cudaFuncAttributeMaxDynamicSharedMemorySize,
                         SMEM_FLASH);
    flash_mma_kernel<<<256, 128, SMEM_FLASH>>>();

    dim3 grid(N / 64, N / 64);
    pairwise_mma_kernel<<<grid, 128>>>(out);
}

// round 16
// speedup vs baseline: 1.2081x; 1.1048x over previous
#include <cuda_runtime.h>
#include <cuda_bf16.h>
#include <cstdint>
#include <math.h>

#define N 8192
#define D 64
#define SCALE 0.125f      // 1/sqrt(64)
#define LSTRIDE 72        // smem row stride in bf16 (144B, conflict-free)
#define LS32 36           // row stride in u32 words
#define RB 144            // row stride in bytes
#define L2E 1.44269504f
#define CEXP 0.18033688f  // SCALE * log2(e)

// ---------------------------------------------------------------------------
// global scratch (no allocation allowed) -- all row-major [n][64] bf16 splits
// ---------------------------------------------------------------------------
__device__ __nv_bfloat16 g_qhi[2][N * D];
__device__ __nv_bfloat16 g_qlo[2][N * D];
__device__ __nv_bfloat16 g_khi[2][N * D];
__device__ __nv_bfloat16 g_klo[2][N * D];
__device__ __nv_bfloat16 g_vhi[2][N * D];    // V (inputs) split, row-major
__device__ __nv_bfloat16 g_vlo[2][N * D];
__device__ __nv_bfloat16 g_atthi[2][N * D];
__device__ __nv_bfloat16 g_attlo[2][N * D];
__device__ float g_norm2[2][N];

// ---------------------------------------------------------------------------
// helpers
// ---------------------------------------------------------------------------
__device__ __forceinline__ uint32_t smem_u32(const void* p) {
    uint32_t a;
    asm("{ .reg .u64 t; cvta.to.shared.u64 t, %1; cvt.u32.u64 %0, t; }" : "=r"(a) : "l"(p));
    return a;
}
__device__ __forceinline__ void mma16816(float* c, const uint32_t* a, const uint32_t* b) {
    asm volatile(
        "mma.sync.aligned.m16n8k16.row.col.f32.bf16.bf16.f32 "
        "{%0,%1,%2,%3}, {%4,%5,%6,%7}, {%8,%9}, {%0,%1,%2,%3};\n"
        : "+f"(c[0]), "+f"(c[1]), "+f"(c[2]), "+f"(c[3])
        : "r"(a[0]), "r"(a[1]), "r"(a[2]), "r"(a[3]), "r"(b[0]), "r"(b[1]));
}
__device__ __forceinline__ void ldmx4(uint32_t* r, uint32_t saddr) {
    asm volatile("ldmatrix.sync.aligned.m8n8.x4.shared.b16 {%0,%1,%2,%3}, [%4];"
        : "=r"(r[0]), "=r"(r[1]), "=r"(r[2]), "=r"(r[3]) : "r"(saddr));
}
__device__ __forceinline__ void ldmx4t(uint32_t* r, uint32_t saddr) {
    asm volatile("ldmatrix.sync.aligned.m8n8.x4.trans.shared.b16 {%0,%1,%2,%3}, [%4];"
        : "=r"(r[0]), "=r"(r[1]), "=r"(r[2]), "=r"(r[3]) : "r"(saddr));
}
__device__ __forceinline__ void cp16(uint32_t saddr, const void* gaddr) {
    asm volatile("cp.async.cg.shared.global [%0], [%1], 16;" :: "r"(saddr), "l"(gaddr));
}
#define CP_COMMIT() asm volatile("cp.async.commit_group;" ::: "memory")
template <int n>
__device__ __forceinline__ void cp_wait() {
    asm volatile("cp.async.wait_group %0;" :: "n"(n) : "memory");
}
__device__ __forceinline__ uint32_t pack_bf16x2(float lo, float hi) {
    uint32_t r;
    asm("cvt.rn.bf16x2.f32 %0, %1, %2;" : "=r"(r) : "f"(hi), "f"(lo));
    return r;
}
__device__ __forceinline__ float lo_bf16(uint32_t p) { return __uint_as_float(p << 16); }
__device__ __forceinline__ float hi_bf16(uint32_t p) { return __uint_as_float(p & 0xFFFF0000u); }
__device__ __forceinline__ float ex2(float x) {
    float r;
    asm("ex2.approx.f32 %0, %1;" : "=f"(r) : "f"(x));
    return r;
}

// ---------------------------------------------------------------------------
// kernel 1: Q/K projection + bf16 splits. 512 blocks x 32 rows. (proven: 23us)
// ---------------------------------------------------------------------------
__global__ __launch_bounds__(256) void prep_kernel(const float* __restrict__ x,
                                                   const float* __restrict__ y,
                                                   const float* __restrict__ Wq,
                                                   const float* __restrict__ Wk) {
    __shared__ float sW[2][D * D];   // 32KB
    __shared__ float sIn[32][D];     // 8KB
    int tid = threadIdx.x;
    int b = blockIdx.x;
    int which = (b >= 256) ? 1 : 0;
    const float* in = which ? y : x;
    int row0 = (b & 255) * 32;

    for (int i = tid; i < D * D; i += 256) { sW[0][i] = Wq[i]; sW[1][i] = Wk[i]; }
    for (int u = tid; u < 32 * D; u += 256)
        ((float*)sIn)[u] = in[(size_t)row0 * D + u];
    __syncthreads();

    int c = tid & 63;
    int rg = tid >> 6;
    float accq[8] = {}, acck[8] = {};
#pragma unroll
    for (int k = 0; k < D; k++) {
        float wq = sW[0][k * D + c];
        float wk = sW[1][k * D + c];
#pragma unroll
        for (int i = 0; i < 8; i++) {
            float v = sIn[rg * 8 + i][k];
            accq[i] = fmaf(v, wq, accq[i]);
            acck[i] = fmaf(v, wk, acck[i]);
        }
    }
#pragma unroll
    for (int i = 0; i < 8; i++) {
        int n = row0 + rg * 8 + i;
        __nv_bfloat16 h;
        h = __float2bfloat16(accq[i]);
        g_qhi[which][(size_t)n * D + c] = h;
        g_qlo[which][(size_t)n * D + c] = __float2bfloat16(accq[i] - __bfloat162float(h));
        h = __float2bfloat16(acck[i]);
        g_khi[which][(size_t)n * D + c] = h;
        g_klo[which][(size_t)n * D + c] = __float2bfloat16(acck[i] - __bfloat162float(h));
    }
    uint32_t* vh = (uint32_t*)g_vhi[which];
    uint32_t* vl = (uint32_t*)g_vlo[which];
    for (int u = tid; u < 1024; u += 256) {
        int r = u >> 5, cc = (u & 31) * 2;
        float v0 = sIn[r][cc], v1 = sIn[r][cc + 1];
        uint32_t h = pack_bf16x2(v0, v1);
        size_t idx = ((size_t)(row0 + r) * D + cc) >> 1;
        vh[idx] = h;
        vl[idx] = pack_bf16x2(v0 - lo_bf16(h), v1 - hi_bf16(h));
    }
}

// ---------------------------------------------------------------------------
// kernel 2: single-pass flash attention, depth-3 cp.async ring, 1 barrier/iter
// CTA: 128 threads (4 warps), 64 query rows, 2 CTAs/SM. (round-15 proven)
// ---------------------------------------------------------------------------
#define TILE_B 36864
#define OFF_KH 0
#define OFF_KL 9216
#define OFF_VH 18432
#define OFF_VL 27648
#define SMEM_FLASH (3 * TILE_B)

__device__ __forceinline__ void flash_issue_tile(uint32_t sbu, int buf,
                                                 int which, int j0, int tid) {
    uint32_t bo = sbu + (uint32_t)buf * TILE_B;
#pragma unroll
    for (int u = tid; u < 512; u += 128) {
        int r = u >> 3, ch = u & 7;
        uint32_t so = (uint32_t)r * RB + (uint32_t)ch * 16;
        cp16(bo + OFF_KH + so, g_khi[which] + (size_t)(j0 + r) * D + ch * 8);
        cp16(bo + OFF_KL + so, g_klo[which] + (size_t)(j0 + r) * D + ch * 8);
        cp16(bo + OFF_VH + so, g_vhi[which] + (size_t)(j0 + r) * D + ch * 8);
        cp16(bo + OFF_VL + so, g_vlo[which] + (size_t)(j0 + r) * D + ch * 8);
    }
    CP_COMMIT();
}

__global__ __launch_bounds__(128, 2) void flash_mma_kernel() {
    extern __shared__ char smf[];
    uint32_t sbu = smem_u32(smf);

    int tid = threadIdx.x;
    int w = tid >> 5, lane = tid & 31;
    int q = lane >> 2, c = lane & 3;
    int which = blockIdx.x >> 7;
    int q0 = (blockIdx.x & 127) * 64;
    int rowA = w * 16 + q;

    for (int u = tid; u < 512; u += 128) {
        int r = u >> 3, ch = u & 7;
        *(uint4*)(smf + OFF_KH + r * RB + ch * 16) =
            ((const uint4*)(g_qhi[which] + (size_t)(q0 + r) * D))[ch];
        *(uint4*)(smf + OFF_KL + r * RB + ch * 16) =
            ((const uint4*)(g_qlo[which] + (size_t)(q0 + r) * D))[ch];
    }
    __syncthreads();

    uint32_t aq[2][4][4];
    {
        const uint32_t* ph = (const uint32_t*)(smf + OFF_KH);
        const uint32_t* pl = (const uint32_t*)(smf + OFF_KL);
#pragma unroll
        for (int kk = 0; kk < 4; kk++) {
            int col = kk * 8 + c;
            aq[0][kk][0] = ph[rowA * LS32 + col];
            aq[0][kk][1] = ph[(rowA + 8) * LS32 + col];
            aq[0][kk][2] = ph[rowA * LS32 + col + 4];
            aq[0][kk][3] = ph[(rowA + 8) * LS32 + col + 4];
            aq[1][kk][0] = pl[rowA * LS32 + col];
            aq[1][kk][1] = pl[(rowA + 8) * LS32 + col];
            aq[1][kk][2] = pl[rowA * LS32 + col + 4];
            aq[1][kk][3] = pl[(rowA + 8) * LS32 + col + 4];
        }
    }
    __syncthreads();

    flash_issue_tile(sbu, 0, which, 0, tid);
    flash_issue_tile(sbu, 1, which, 64, tid);

    float o[8][4] = {};
    float m0 = -INFINITY, m1 = -INFINITY;
    float l0a = 0.f, l0b = 0.f, l1a = 0.f, l1b = 0.f;
    uint32_t lmoff = (uint32_t)(lane & 7) * RB + (uint32_t)(lane >> 3) * 16;

    int bi = 0, bi2 = 2;
    for (int t = 0; t < 128; t++) {
        if (t < 126) cp_wait<1>(); else cp_wait<0>();
        __syncthreads();
        if (t + 2 < 128) flash_issue_tile(sbu, bi2, which, (t + 2) * 64, tid);
        uint32_t bufb = sbu + (uint32_t)bi * TILE_B;
        bi = (bi == 2) ? 0 : bi + 1;
        bi2 = (bi2 == 2) ? 0 : bi2 + 1;

        // ---- S = Q K^T (3 split passes: hh, hl, lh) ----
        float sc[8][4] = {};
#pragma unroll
        for (int nt = 0; nt < 8; nt++) {
            uint32_t a0 = bufb + (uint32_t)nt * (8 * RB) + lmoff;
            uint32_t bh[4][2], bl[4][2];
            ldmx4(&bh[0][0], a0 + OFF_KH);
            ldmx4(&bh[2][0], a0 + OFF_KH + 64);
            ldmx4(&bl[0][0], a0 + OFF_KL);
            ldmx4(&bl[2][0], a0 + OFF_KL + 64);
#pragma unroll
            for (int kk = 0; kk < 4; kk++) mma16816(sc[nt], aq[0][kk], bh[kk]);
#pragma unroll
            for (int kk = 0; kk < 4; kk++) mma16816(sc[nt], aq[0][kk], bl[kk]);
#pragma unroll
            for (int kk = 0; kk < 4; kk++) mma16816(sc[nt], aq[1][kk], bh[kk]);
        }

        // ---- online softmax (ex2-based) ----
        float mx0 = -INFINITY, mx1 = -INFINITY;
#pragma unroll
        for (int nt = 0; nt < 8; nt++) {
            mx0 = fmaxf(mx0, fmaxf(sc[nt][0], sc[nt][1]));
            mx1 = fmaxf(mx1, fmaxf(sc[nt][2], sc[nt][3]));
        }
        mx0 = fmaxf(mx0, __shfl_xor_sync(0xffffffffu, mx0, 1));
        mx0 = fmaxf(mx0, __shfl_xor_sync(0xffffffffu, mx0, 2));
        mx1 = fmaxf(mx1, __shfl_xor_sync(0xffffffffu, mx1, 1));
        mx1 = fmaxf(mx1, __shfl_xor_sync(0xffffffffu, mx1, 2));
        float m0n = fmaxf(m0, mx0), m1n = fmaxf(m1, mx1);
        float f0 = ex2((m0 - m0n) * CEXP);
        float f1 = ex2((m1 - m1n) * CEXP);
        m0 = m0n; m1 = m1n;
        float nmc0 = -m0n * CEXP, nmc1 = -m1n * CEXP;
        l0a *= f0; l0b *= f0; l1a *= f1; l1b *= f1;

        uint32_t pah[8], pbh[8], pal[8], pbl[8];
#pragma unroll
        for (int nt = 0; nt < 8; nt++) {
            float p0 = ex2(fmaf(sc[nt][0], CEXP, nmc0));
            float p1 = ex2(fmaf(sc[nt][1], CEXP, nmc0));
            float p2 = ex2(fmaf(sc[nt][2], CEXP, nmc1));
            float p3 = ex2(fmaf(sc[nt][3], CEXP, nmc1));
            l0a += p0; l0b += p1; l1a += p2; l1b += p3;
            uint32_t h = pack_bf16x2(p0, p1);
            pah[nt] = h;
            pal[nt] = pack_bf16x2(p0 - lo_bf16(h), p1 - hi_bf16(h));
            h = pack_bf16x2(p2, p3);
            pbh[nt] = h;
            pbl[nt] = pack_bf16x2(p2 - lo_bf16(h), p3 - hi_bf16(h));
            o[nt][0] *= f0; o[nt][1] *= f0; o[nt][2] *= f1; o[nt][3] *= f1;
        }

        // ---- O += P V (3 split passes), row-major V via ldmatrix.trans ----
#pragma unroll
        for (int nt = 0; nt < 8; nt++) {
            uint32_t av = bufb + OFF_VH + (uint32_t)lane * RB + (uint32_t)nt * 16;
            uint32_t vbh[4][2], vbl[4][2];
            ldmx4t(&vbh[0][0], av);
            ldmx4t(&vbh[2][0], av + 32 * RB);
            ldmx4t(&vbl[0][0], av + (OFF_VL - OFF_VH));
            ldmx4t(&vbl[2][0], av + (OFF_VL - OFF_VH) + 32 * RB);
#pragma unroll
            for (int kk = 0; kk < 4; kk++) {
                uint32_t Ah[4] = {pah[2 * kk], pbh[2 * kk], pah[2 * kk + 1], pbh[2 * kk + 1]};
                uint32_t Al[4] = {pal[2 * kk], pbl[2 * kk], pal[2 * kk + 1], pbl[2 * kk + 1]};
                mma16816(o[nt], Ah, vbh[kk]);
                mma16816(o[nt], Ah, vbl[kk]);
                mma16816(o[nt], Al, vbh[kk]);
            }
        }
    }

    // ---- epilogue ----
    float l0 = l0a + l0b, l1 = l1a + l1b;
    l0 += __shfl_xor_sync(0xffffffffu, l0, 1);
    l0 += __shfl_xor_sync(0xffffffffu, l0, 2);
    l1 += __shfl_xor_sync(0xffffffffu, l1, 1);
    l1 += __shfl_xor_sync(0xffffffffu, l1, 2);
    float inv0 = 1.0f / l0, inv1 = 1.0f / l1;
    float n0 = 0.f, n1 = 0.f;
    int row = q0 + rowA;
    uint32_t* dh = (uint32_t*)g_atthi[which];
    uint32_t* dl = (uint32_t*)g_attlo[which];
#pragma unroll
    for (int nt = 0; nt < 8; nt++) {
        float o0 = o[nt][0] * inv0, o1 = o[nt][1] * inv0;
        float o2 = o[nt][2] * inv1, o3 = o[nt][3] * inv1;
        n0 = fmaf(o0, o0, fmaf(o1, o1, n0));
        n1 = fmaf(o2, o2, fmaf(o3, o3, n1));
        uint32_t h = pack_bf16x2(o0, o1);
        dh[(size_t)row * 32 + nt * 4 + c] = h;
        dl[(size_t)row * 32 + nt * 4 + c] = pack_bf16x2(o0 - lo_bf16(h), o1 - hi_bf16(h));
        h = pack_bf16x2(o2, o3);
        dh[(size_t)(row + 8) * 32 + nt * 4 + c] = h;
        dl[(size_t)(row + 8) * 32 + nt * 4 + c] = pack_bf16x2(o2 - lo_bf16(h), o3 - hi_bf16(h));
    }
    n0 += __shfl_xor_sync(0xffffffffu, n0, 1);
    n0 += __shfl_xor_sync(0xffffffffu, n0, 2);
    n1 += __shfl_xor_sync(0xffffffffu, n1, 1);
    n1 += __shfl_xor_sync(0xffffffffu, n1, 2);
    if (c == 0) {
        g_norm2[which][row] = n0;
        g_norm2[which][row + 8] = n1;
    }
}

// ---------------------------------------------------------------------------
// kernel 3: pairwise RBF, 64x64 tiles, PJ=4 j-tiles per CTA with A reuse.
// CONSERVATIVE ring: at most ONE cp.async group in flight at any time.
// A via plain loads (once). B double-buffered: wait<0> + barrier, then issue
// next B so its load overlaps this tile's MMA+epilogue.
// smem: A hi 0 / lo 9216; B ring 2 x 18432 at 18432; syn(256f) 55296.
// ---------------------------------------------------------------------------
#define PJ 4
#define PW_A 0
#define PW_B0 18432
#define PW_BUF 18432
#define PW_SYN 55296
#define SMEM_PW (55296 + 1024)

__device__ __forceinline__ void pw_issue_B(uint32_t sbu, int buf, int j0, int tid) {
    uint32_t bo = sbu + PW_B0 + (uint32_t)buf * PW_BUF;
#pragma unroll
    for (int u = tid; u < 512; u += 128) {
        int r = u >> 3, ch = u & 7;
        uint32_t so = (uint32_t)r * RB + (uint32_t)ch * 16;
        cp16(bo + so, g_atthi[1] + (size_t)(j0 + r) * D + ch * 8);
        cp16(bo + 9216 + so, g_attlo[1] + (size_t)(j0 + r) * D + ch * 8);
    }
    CP_COMMIT();
}

__global__ __launch_bounds__(128, 3) void pairwise_mma_kernel(float* __restrict__ out) {
    extern __shared__ char smp[];
    uint32_t sbu = smem_u32(smp);

    int tid = threadIdx.x;
    int w = tid >> 5, lane = tid & 31;
    int q = lane >> 2, c = lane & 3;
    int m0 = blockIdx.y * 64;
    int j0base = blockIdx.x * (64 * PJ);
    int rowA = w * 16 + q;

    // B0: the only cp.async group in flight
    pw_issue_B(sbu, 0, j0base, tid);

    // A tile + norms: plain loads (no async accounting)
    for (int u = tid; u < 512; u += 128) {
        int r = u >> 3, ch = u & 7;
        uint32_t so = (uint32_t)r * RB + (uint32_t)ch * 16;
        *(uint4*)(smp + PW_A + so) =
            ((const uint4*)(g_atthi[0] + (size_t)(m0 + r) * D))[ch];
        *(uint4*)(smp + PW_A + 9216 + so) =
            ((const uint4*)(g_attlo[0] + (size_t)(m0 + r) * D))[ch];
    }
    float* syn = (float*)(smp + PW_SYN);
    {
        float2 t = ((const float2*)(g_norm2[1] + j0base))[tid];   // 256 norms
        syn[2 * tid] = t.x * L2E;
        syn[2 * tid + 1] = t.y * L2E;
    }
    __syncthreads();   // A + syn visible

    uint32_t aq[2][4][4];
    {
        const uint32_t* ph = (const uint32_t*)(smp + PW_A);
        const uint32_t* pl = (const uint32_t*)(smp + PW_A + 9216);
#pragma unroll
        for (int kk = 0; kk < 4; kk++) {
            int col = kk * 8 + c;
            aq[0][kk][0] = ph[rowA * LS32 + col];
            aq[0][kk][1] = ph[(rowA + 8) * LS32 + col];
            aq[0][kk][2] = ph[rowA * LS32 + col + 4];
            aq[0][kk][3] = ph[(rowA + 8) * LS32 + col + 4];
            aq[1][kk][0] = pl[rowA * LS32 + col];
            aq[1][kk][1] = pl[(rowA + 8) * LS32 + col];
            aq[1][kk][2] = pl[rowA * LS32 + col + 4];
            aq[1][kk][3] = pl[(rowA + 8) * LS32 + col + 4];
        }
    }

    int rowx = m0 + rowA;
    float xnL0 = g_norm2[0][rowx] * L2E;
    float xnL1 = g_norm2[0][rowx + 8] * L2E;
    uint32_t lmoff = (uint32_t)(lane & 7) * RB + (uint32_t)(lane >> 3) * 16;
    const float TWOC = 2.0f * L2E;

#pragma unroll 1
    for (int jt = 0; jt < PJ; jt++) {
        cp_wait<0>();          // drain B(jt) -- the single in-flight group
        __syncthreads();
        // overlap: start B(jt+1) into the other buffer (its readers finished
        // at the end of iteration jt-1, before the barrier above)
        if (jt + 1 < PJ) pw_issue_B(sbu, (jt + 1) & 1, j0base + (jt + 1) * 64, tid);

        uint32_t sbh = sbu + PW_B0 + (uint32_t)(jt & 1) * PW_BUF;
        uint32_t sbl = sbh + 9216;

        float acc[8][4] = {};
#pragma unroll
        for (int nt = 0; nt < 8; nt++) {
            uint32_t ro = (uint32_t)nt * (8 * RB) + lmoff;
            uint32_t bh[4][2], bl[4][2];
            ldmx4(&bh[0][0], sbh + ro);
            ldmx4(&bh[2][0], sbh + ro + 64);
            ldmx4(&bl[0][0], sbl + ro);
            ldmx4(&bl[2][0], sbl + ro + 64);
#pragma unroll
            for (int kk = 0; kk < 4; kk++) mma16816(acc[nt], aq[0][kk], bh[kk]);
#pragma unroll
            for (int kk = 0; kk < 4; kk++) mma16816(acc[nt], aq[0][kk], bl[kk]);
#pragma unroll
            for (int kk = 0; kk < 4; kk++) mma16816(acc[nt], aq[1][kk], bh[kk]);
        }

        int j0 = j0base + jt * 64;
        const float* sy = syn + jt * 64;
#pragma unroll
        for (int nt = 0; nt < 8; nt++) {
            int cb = nt * 8 + 2 * c;
            float y0 = sy[cb], y1 = sy[cb + 1];
            float2 e;
            e.x = ex2(fmaf(acc[nt][0], TWOC, -(xnL0 + y0)));
            e.y = ex2(fmaf(acc[nt][1], TWOC, -(xnL0 + y1)));
            *reinterpret_cast<float2*>(out + (size_t)rowx * N + j0 + cb) = e;
            e.x = ex2(fmaf(acc[nt][2], TWOC, -(xnL1 + y0)));
            e.y = ex2(fmaf(acc[nt][3], TWOC, -(xnL1 + y1)));
            *reinterpret_cast<float2*>(out + (size_t)(rowx + 8) * N + j0 + cb) = e;
        }
        __syncthreads();   // all reads of buffer (jt&1) complete before reuse
    }
}

// ---------------------------------------------------------------------------
extern "C" void kernel_launch(void* const* d_in, const int* in_sizes, int n_in,
                              void* d_out, int out_size) {
    const float* Wq = (const float*)d_in[0];
    const float* Wk = (const float*)d_in[1];
    const float* x  = (const float*)d_in[2];
    const float* y  = (const float*)d_in[3];
    float* out = (float*)d_out;

    prep_kernel<<<512, 256>>>(x, y, Wq, Wk);

    cudaFuncSetAttribute(flash_mma_kernel, cudaFuncAttributeMaxDynamicSharedMemorySize,
                         SMEM_FLASH);
    flash_mma_kernel<<<256, 128, SMEM_FLASH>>>();

    cudaFuncSetAttribute(pairwise_mma_kernel, cudaFuncAttributeMaxDynamicSharedMemorySize,
                         SMEM_PW);
    dim3 grid(N / (64 * PJ), N / 64);
    pairwise_mma_kernel<<<grid, 128, SMEM_PW>>>(out);
}